// round 1
// baseline (speedup 1.0000x reference)
#include <cuda_runtime.h>
#include <math.h>

#define NN  100000
#define NE  800000
#define FND 128
#define FED 16
#define HD  200
#define NTW 8
#define DTW 25
#define NG  64
#define NSTEPS 3
#define RT  16     // node rows per block (GEMM tiles)
#define RE  32     // edge rows per block (edge gate)

// ---------------- scratch (static device memory; no allocation) ----------------
__device__ float     g_h[(size_t)NN * HD];       // 80 MB
__device__ float     g_agg[(size_t)NN * HD];     // 80 MB
__device__ float     g_eg[(size_t)NE * HD];      // 640 MB
__device__ float     g_score[NN];
__device__ float     g_ex[NN];
__device__ unsigned  g_smax[NG];
__device__ float     g_denom[NG];
__device__ float     g_gfeat[NG * HD];

__device__ __forceinline__ float sigf(float x) { return 1.0f / (1.0f + __expf(-x)); }

// order-preserving float<->uint encoding for atomicMax on floats
__device__ __forceinline__ unsigned enc_f(float f) {
    unsigned u = __float_as_uint(f);
    return (u & 0x80000000u) ? ~u : (u | 0x80000000u);
}
__device__ __forceinline__ float dec_f(unsigned u) {
    u = (u & 0x80000000u) ? (u & 0x7FFFFFFFu) : ~u;
    return __uint_as_float(u);
}

// ---------------- h0 = relu(X @ W_in + b_in) ----------------
__global__ void k_h0(const float* __restrict__ X, const float* __restrict__ W,
                     const float* __restrict__ b) {
    __shared__ float sX[RT][FND];
    int base = blockIdx.x * RT;
    const float4* src = (const float4*)(X + (size_t)base * FND);
    for (int i = threadIdx.x; i < RT * FND / 4; i += blockDim.x)
        ((float4*)sX)[i] = src[i];
    __syncthreads();
    int j = threadIdx.x;
    if (j >= HD) return;
    float acc[RT];
#pragma unroll
    for (int i = 0; i < RT; i++) acc[i] = b[j];
    for (int k = 0; k < FND; k += 4) {
        float w0 = W[(k + 0) * HD + j], w1 = W[(k + 1) * HD + j];
        float w2 = W[(k + 2) * HD + j], w3 = W[(k + 3) * HD + j];
#pragma unroll
        for (int i = 0; i < RT; i++) {
            float4 x4 = *(const float4*)&sX[i][k];
            acc[i] += x4.x * w0 + x4.y * w1 + x4.z * w2 + x4.w * w3;
        }
    }
#pragma unroll
    for (int i = 0; i < RT; i++)
        g_h[(size_t)(base + i) * HD + j] = fmaxf(acc[i], 0.0f);
}

// ---------------- edge_gate = sigmoid(EF @ W_edge + b_edge) ----------------
__global__ void k_eg(const float* __restrict__ EF, const float* __restrict__ W,
                     const float* __restrict__ b) {
    __shared__ float sX[RE][FED];
    int base = blockIdx.x * RE;
    const float4* src = (const float4*)(EF + (size_t)base * FED);
    for (int i = threadIdx.x; i < RE * FED / 4; i += blockDim.x)
        ((float4*)sX)[i] = src[i];
    __syncthreads();
    int j = threadIdx.x;
    if (j >= HD) return;
    float acc[RE];
#pragma unroll
    for (int i = 0; i < RE; i++) acc[i] = b[j];
#pragma unroll
    for (int k = 0; k < FED; k++) {
        float w = W[k * HD + j];
#pragma unroll
        for (int i = 0; i < RE; i++) acc[i] += sX[i][k] * w;
    }
#pragma unroll
    for (int i = 0; i < RE; i++)
        g_eg[(size_t)(base + i) * HD + j] = sigf(acc[i]);
}

// ---------------- zero agg ----------------
__global__ void k_zero_agg() {
    int i = blockIdx.x * blockDim.x + threadIdx.x;
    if (i < NN * HD / 4) ((float4*)g_agg)[i] = make_float4(0.f, 0.f, 0.f, 0.f);
}

// ---------------- scatter: agg[dst] += eg[e] * h[src] ----------------
__global__ void k_scatter(const int* __restrict__ ei) {
    int idx = blockIdx.x * blockDim.x + threadIdx.x;
    if (idx >= NE * (HD / 4)) return;
    int e = idx / (HD / 4);
    int c = (idx - e * (HD / 4)) * 4;
    int s = ei[e];
    int d = ei[NE + e];
    float4 eg = *(const float4*)&g_eg[(size_t)e * HD + c];
    float4 hv = *(const float4*)&g_h[(size_t)s * HD + c];
    float* p = &g_agg[(size_t)d * HD + c];
    atomicAdd(p + 0, eg.x * hv.x);
    atomicAdd(p + 1, eg.y * hv.y);
    atomicAdd(p + 2, eg.z * hv.z);
    atomicAdd(p + 3, eg.w * hv.w);
}

// ---------------- fused tower + mix + GRU update ----------------
__global__ void k_gru(const float* __restrict__ Wt,
                      const float* __restrict__ Wmix, const float* __restrict__ bmix,
                      const float* __restrict__ Wz, const float* __restrict__ Uz, const float* __restrict__ bz,
                      const float* __restrict__ Wr, const float* __restrict__ Ur, const float* __restrict__ br,
                      const float* __restrict__ Wh, const float* __restrict__ Uh, const float* __restrict__ bh) {
    __shared__ float sA[RT][HD];   // agg -> then m
    __shared__ float sT[RT][HD];   // tower out -> then r*h
    __shared__ float sH[RT][HD];   // h
    int base = blockIdx.x * RT;
    {
        const float4* a4 = (const float4*)(g_agg + (size_t)base * HD);
        const float4* h4 = (const float4*)(g_h + (size_t)base * HD);
        for (int i = threadIdx.x; i < RT * HD / 4; i += blockDim.x) {
            ((float4*)sA)[i] = a4[i];
            ((float4*)sH)[i] = h4[i];
        }
    }
    __syncthreads();

    int j = threadIdx.x;
    bool act = (j < HD);
    float zv[RT];

    // ---- tower mixing: sT[n][t*25+e] = sum_d sA[n][t*25+d] * Wt[t][d][e] ----
    if (act) {
        int t = j / DTW, e = j % DTW;
        const float* wt = Wt + (t * DTW) * DTW + e;
        float acc[RT];
#pragma unroll
        for (int i = 0; i < RT; i++) acc[i] = 0.0f;
#pragma unroll
        for (int d = 0; d < DTW; d++) {
            float w = wt[d * DTW];
            int kk = t * DTW + d;
#pragma unroll
            for (int i = 0; i < RT; i++) acc[i] += sA[i][kk] * w;
        }
#pragma unroll
        for (int i = 0; i < RT; i++) sT[i][j] = acc[i];
    }
    __syncthreads();

    // ---- m = relu(sT @ Wmix + bmix) -> sA ----
    if (act) {
        float acc[RT];
#pragma unroll
        for (int i = 0; i < RT; i++) acc[i] = bmix[j];
        for (int k = 0; k < HD; k += 4) {
            float w0 = Wmix[(k + 0) * HD + j], w1 = Wmix[(k + 1) * HD + j];
            float w2 = Wmix[(k + 2) * HD + j], w3 = Wmix[(k + 3) * HD + j];
#pragma unroll
            for (int i = 0; i < RT; i++) {
                float4 a = *(const float4*)&sT[i][k];
                acc[i] += a.x * w0 + a.y * w1 + a.z * w2 + a.w * w3;
            }
        }
#pragma unroll
        for (int i = 0; i < RT; i++) sA[i][j] = fmaxf(acc[i], 0.0f);
    }
    __syncthreads();

    // ---- z = sig(m@Wz + h@Uz + bz), r = sig(m@Wr + h@Ur + br); sT = r*h ----
    if (act) {
        float accZ[RT], accR[RT];
#pragma unroll
        for (int i = 0; i < RT; i++) { accZ[i] = bz[j]; accR[i] = br[j]; }
        for (int k = 0; k < HD; k += 4) {
            float wz0 = Wz[(k + 0) * HD + j], wz1 = Wz[(k + 1) * HD + j];
            float wz2 = Wz[(k + 2) * HD + j], wz3 = Wz[(k + 3) * HD + j];
            float uz0 = Uz[(k + 0) * HD + j], uz1 = Uz[(k + 1) * HD + j];
            float uz2 = Uz[(k + 2) * HD + j], uz3 = Uz[(k + 3) * HD + j];
            float wr0 = Wr[(k + 0) * HD + j], wr1 = Wr[(k + 1) * HD + j];
            float wr2 = Wr[(k + 2) * HD + j], wr3 = Wr[(k + 3) * HD + j];
            float ur0 = Ur[(k + 0) * HD + j], ur1 = Ur[(k + 1) * HD + j];
            float ur2 = Ur[(k + 2) * HD + j], ur3 = Ur[(k + 3) * HD + j];
#pragma unroll
            for (int i = 0; i < RT; i++) {
                float4 m4 = *(const float4*)&sA[i][k];
                float4 h4 = *(const float4*)&sH[i][k];
                accZ[i] += m4.x * wz0 + m4.y * wz1 + m4.z * wz2 + m4.w * wz3
                         + h4.x * uz0 + h4.y * uz1 + h4.z * uz2 + h4.w * uz3;
                accR[i] += m4.x * wr0 + m4.y * wr1 + m4.z * wr2 + m4.w * wr3
                         + h4.x * ur0 + h4.y * ur1 + h4.z * ur2 + h4.w * ur3;
            }
        }
#pragma unroll
        for (int i = 0; i < RT; i++) {
            zv[i] = sigf(accZ[i]);
            float r = sigf(accR[i]);
            sT[i][j] = r * sH[i][j];
        }
    }
    __syncthreads();

    // ---- h~ = tanh(m@Wh + (r*h)@Uh + bh); h = (1-z)h + z*h~ ----
    if (act) {
        float acc[RT];
#pragma unroll
        for (int i = 0; i < RT; i++) acc[i] = bh[j];
        for (int k = 0; k < HD; k += 4) {
            float w0 = Wh[(k + 0) * HD + j], w1 = Wh[(k + 1) * HD + j];
            float w2 = Wh[(k + 2) * HD + j], w3 = Wh[(k + 3) * HD + j];
            float u0 = Uh[(k + 0) * HD + j], u1 = Uh[(k + 1) * HD + j];
            float u2 = Uh[(k + 2) * HD + j], u3 = Uh[(k + 3) * HD + j];
#pragma unroll
            for (int i = 0; i < RT; i++) {
                float4 m4 = *(const float4*)&sA[i][k];
                float4 t4 = *(const float4*)&sT[i][k];
                acc[i] += m4.x * w0 + m4.y * w1 + m4.z * w2 + m4.w * w3
                        + t4.x * u0 + t4.y * u1 + t4.z * u2 + t4.w * u3;
            }
        }
#pragma unroll
        for (int i = 0; i < RT; i++) {
            float ht = tanhf(acc[i]);
            g_h[(size_t)(base + i) * HD + j] = (1.0f - zv[i]) * sH[i][j] + zv[i] * ht;
        }
    }
}

// ---------------- init readout scratch ----------------
__global__ void k_init_small() {
    int t = blockIdx.x * blockDim.x + threadIdx.x;
    for (int i = t; i < NG * HD; i += gridDim.x * blockDim.x) g_gfeat[i] = 0.0f;
    if (t < NG) { g_denom[t] = 0.0f; g_smax[t] = enc_f(-INFINITY); }
}

// ---------------- score + segment max ----------------
__global__ void k_score(const float* __restrict__ Ws, const float* __restrict__ bs,
                        const int* __restrict__ bv) {
    int n = blockIdx.x * 8 + (threadIdx.x >> 5);
    if (n >= NN) return;
    int lane = threadIdx.x & 31;
    float acc = 0.0f;
    for (int k = lane; k < HD; k += 32) acc += g_h[(size_t)n * HD + k] * Ws[k];
#pragma unroll
    for (int o = 16; o; o >>= 1) acc += __shfl_xor_sync(0xffffffffu, acc, o);
    if (lane == 0) {
        float s = acc + bs[0];
        g_score[n] = s;
        atomicMax(&g_smax[bv[n]], enc_f(s));
    }
}

// ---------------- exp + segment sum (run-length aggregated) ----------------
__global__ void k_exp(const int* __restrict__ bv) {
    int n0 = (blockIdx.x * blockDim.x + threadIdx.x) * 16;
    if (n0 >= NN) return;
    int end = n0 + 16; if (end > NN) end = NN;
    int cb = bv[n0];
    float mx = dec_f(g_smax[cb]);
    float run = 0.0f;
    for (int n = n0; n < end; n++) {
        int b = bv[n];
        if (b != cb) {
            atomicAdd(&g_denom[cb], run);
            run = 0.0f; cb = b; mx = dec_f(g_smax[b]);
        }
        float ex = __expf(g_score[n] - mx);
        g_ex[n] = ex;
        run += ex;
    }
    atomicAdd(&g_denom[cb], run);
}

// ---------------- feat = h@W_feat + b_feat; g[b] += alpha * feat ----------------
__global__ void k_feat(const float* __restrict__ Wf, const float* __restrict__ bf,
                       const int* __restrict__ bv) {
    __shared__ float sHt[RT][HD];
    __shared__ float sAl[RT];
    __shared__ int   sB[RT];
    int base = blockIdx.x * RT;
    {
        const float4* h4 = (const float4*)(g_h + (size_t)base * HD);
        for (int i = threadIdx.x; i < RT * HD / 4; i += blockDim.x)
            ((float4*)sHt)[i] = h4[i];
    }
    if (threadIdx.x < RT) {
        int n = base + threadIdx.x;
        int b = bv[n];
        sB[threadIdx.x] = b;
        sAl[threadIdx.x] = g_ex[n] / g_denom[b];
    }
    __syncthreads();
    int j = threadIdx.x;
    if (j >= HD) return;
    float acc[RT];
#pragma unroll
    for (int i = 0; i < RT; i++) acc[i] = bf[j];
    for (int k = 0; k < HD; k += 4) {
        float w0 = Wf[(k + 0) * HD + j], w1 = Wf[(k + 1) * HD + j];
        float w2 = Wf[(k + 2) * HD + j], w3 = Wf[(k + 3) * HD + j];
#pragma unroll
        for (int i = 0; i < RT; i++) {
            float4 h4 = *(const float4*)&sHt[i][k];
            acc[i] += h4.x * w0 + h4.y * w1 + h4.z * w2 + h4.w * w3;
        }
    }
    // run-length aggregate atomics (batch_vector is sorted)
    float run = 0.0f;
    int cb = sB[0];
#pragma unroll
    for (int i = 0; i < RT; i++) {
        if (sB[i] != cb) {
            atomicAdd(&g_gfeat[cb * HD + j], run);
            run = 0.0f; cb = sB[i];
        }
        run += sAl[i] * acc[i];
    }
    atomicAdd(&g_gfeat[cb * HD + j], run);
}

// ---------------- readout MLP: out = relu(g@W_r1+b_r1)@W_out + b_out ----------------
__global__ void k_readout(const float* __restrict__ Wr1, const float* __restrict__ br1,
                          const float* __restrict__ Wout, const float* __restrict__ bout,
                          float* __restrict__ out) {
    __shared__ float sG[HD];
    __shared__ float sRed[256];
    int g = blockIdx.x;
    for (int k = threadIdx.x; k < HD; k += blockDim.x) sG[k] = g_gfeat[g * HD + k];
    __syncthreads();
    float p = 0.0f;
    int j = threadIdx.x;
    if (j < HD) {
        float acc = br1[j];
        for (int k = 0; k < HD; k++) acc += sG[k] * Wr1[k * HD + j];
        p = fmaxf(acc, 0.0f) * Wout[j];
    }
    sRed[threadIdx.x] = p;
    __syncthreads();
    for (int s = 128; s; s >>= 1) {
        if (threadIdx.x < s) sRed[threadIdx.x] += sRed[threadIdx.x + s];
        __syncthreads();
    }
    if (threadIdx.x == 0) out[g] = sRed[0] + bout[0];
}

// ---------------- launch ----------------
extern "C" void kernel_launch(void* const* d_in, const int* in_sizes, int n_in,
                              void* d_out, int out_size) {
    const float* node_features = (const float*)d_in[0];
    const float* edge_features = (const float*)d_in[1];
    const int*   edge_index    = (const int*)d_in[2];
    const int*   batch_vector  = (const int*)d_in[3];
    const float* W_in   = (const float*)d_in[4];
    const float* b_in   = (const float*)d_in[5];
    const float* W_edge = (const float*)d_in[6];
    const float* b_edge = (const float*)d_in[7];
    const float* W_tower= (const float*)d_in[8];
    const float* W_mix  = (const float*)d_in[9];
    const float* b_mix  = (const float*)d_in[10];
    const float* Wz = (const float*)d_in[11];
    const float* Uz = (const float*)d_in[12];
    const float* bz = (const float*)d_in[13];
    const float* Wr = (const float*)d_in[14];
    const float* Ur = (const float*)d_in[15];
    const float* br = (const float*)d_in[16];
    const float* Wh = (const float*)d_in[17];
    const float* Uh = (const float*)d_in[18];
    const float* bh = (const float*)d_in[19];
    const float* W_score = (const float*)d_in[20];
    const float* b_score = (const float*)d_in[21];
    const float* W_feat  = (const float*)d_in[22];
    const float* b_feat  = (const float*)d_in[23];
    const float* W_r1    = (const float*)d_in[24];
    const float* b_r1    = (const float*)d_in[25];
    const float* W_out   = (const float*)d_in[26];
    const float* b_out   = (const float*)d_in[27];
    float* out = (float*)d_out;

    k_h0<<<NN / RT, 224>>>(node_features, W_in, b_in);
    k_eg<<<NE / RE, 224>>>(edge_features, W_edge, b_edge);

    for (int s = 0; s < NSTEPS; s++) {
        k_zero_agg<<<(NN * HD / 4 + 255) / 256, 256>>>();
        k_scatter<<<(NE * (HD / 4) + 255) / 256, 256>>>(edge_index);
        k_gru<<<NN / RT, 224>>>(W_tower, W_mix, b_mix,
                                Wz, Uz, bz, Wr, Ur, br, Wh, Uh, bh);
    }

    k_init_small<<<50, 256>>>();
    k_score<<<(NN + 7) / 8, 256>>>(W_score, b_score, batch_vector);
    k_exp<<<(NN / 16 + 255) / 256, 256>>>(batch_vector);
    k_feat<<<NN / RT, 224>>>(W_feat, b_feat, batch_vector);
    k_readout<<<NG, 256>>>(W_r1, b_r1, W_out, b_out, out);
}